// round 2
// baseline (speedup 1.0000x reference)
#include <cuda_runtime.h>
#include <cuda_bf16.h>
#include <math.h>

// ForMicroLoss: l = sum_{pos} softplus(-x)/n_pos + sum_{neg} softplus(x)/n_neg
// pred_y: fp32 [N*K], true_y: int32 [N*K] (values in {0,1})
// Memory-bound streaming reduction: 512 MB read, 4 B write.

#define NBLOCKS 2048
#define NTHREADS 256

// Deterministic per-block partials (no fp32 atomics). __device__ globals per
// the no-allocation rule.
__device__ float g_pos_part[NBLOCKS];
__device__ float g_neg_part[NBLOCKS];
__device__ int   g_cnt_part[NBLOCKS];   // count of pos labels in this block's slice

// softplus pieces:
//   t = log1p(exp(-|x|))          (shared between both label cases)
//   pos contributes softplus(-x) = t + max(-x, 0)
//   neg contributes softplus( x) = t + max( x, 0)
// Branchless: predicated adds, no BSSY/BSYNC.
__device__ __forceinline__ void accum_elem(float x, int lbl,
                                           float& pos_acc, float& neg_acc) {
    float t = log1pf(__expf(-fabsf(x)));
    float relu_p = fmaxf(-x, 0.0f);   // extra piece for pos case
    float relu_n = fmaxf( x, 0.0f);   // extra piece for neg case
    bool is_pos = (lbl != 0);
    pos_acc += is_pos ? (t + relu_p) : 0.0f;
    neg_acc += is_pos ? 0.0f : (t + relu_n);
}

__global__ __launch_bounds__(NTHREADS)
void micro_loss_partial_kernel(const float* __restrict__ pred,
                               const int*   __restrict__ lbl,
                               long long n) {
    const long long tid    = (long long)blockIdx.x * blockDim.x + threadIdx.x;
    const long long stride = (long long)gridDim.x * blockDim.x;

    float pos_acc = 0.0f, neg_acc = 0.0f;
    int cnt = 0;

    // Vectorized main loop: 16B loads for both streams, labels counted by
    // integer summation (labels are exactly 0/1).
    const long long n4 = n >> 2;
    const float4* __restrict__ pred4 = reinterpret_cast<const float4*>(pred);
    const int4*   __restrict__ lbl4  = reinterpret_cast<const int4*>(lbl);

    for (long long i = tid; i < n4; i += stride) {
        float4 p = pred4[i];
        int4   l = lbl4[i];
        cnt += l.x + l.y + l.z + l.w;
        accum_elem(p.x, l.x, pos_acc, neg_acc);
        accum_elem(p.y, l.y, pos_acc, neg_acc);
        accum_elem(p.z, l.z, pos_acc, neg_acc);
        accum_elem(p.w, l.w, pos_acc, neg_acc);
    }
    // Tail (n not divisible by 4) — not hit at 8192x8192 but kept for safety.
    for (long long i = (n4 << 2) + tid; i < n; i += stride) {
        float x = pred[i];
        int   l = lbl[i];
        cnt += l;
        accum_elem(x, l, pos_acc, neg_acc);
    }

    // Warp reduce
    #pragma unroll
    for (int off = 16; off > 0; off >>= 1) {
        pos_acc += __shfl_down_sync(0xffffffffu, pos_acc, off);
        neg_acc += __shfl_down_sync(0xffffffffu, neg_acc, off);
        cnt     += __shfl_down_sync(0xffffffffu, cnt,     off);
    }

    // Block reduce via shared memory
    __shared__ float s_pos[NTHREADS / 32];
    __shared__ float s_neg[NTHREADS / 32];
    __shared__ int   s_cnt[NTHREADS / 32];
    int lane = threadIdx.x & 31;
    int warp = threadIdx.x >> 5;
    if (lane == 0) {
        s_pos[warp] = pos_acc;
        s_neg[warp] = neg_acc;
        s_cnt[warp] = cnt;
    }
    __syncthreads();
    if (warp == 0) {
        pos_acc = (lane < NTHREADS / 32) ? s_pos[lane] : 0.0f;
        neg_acc = (lane < NTHREADS / 32) ? s_neg[lane] : 0.0f;
        cnt     = (lane < NTHREADS / 32) ? s_cnt[lane] : 0;
        #pragma unroll
        for (int off = 16; off > 0; off >>= 1) {
            pos_acc += __shfl_down_sync(0xffffffffu, pos_acc, off);
            neg_acc += __shfl_down_sync(0xffffffffu, neg_acc, off);
            cnt     += __shfl_down_sync(0xffffffffu, cnt,     off);
        }
        if (lane == 0) {
            g_pos_part[blockIdx.x] = pos_acc;
            g_neg_part[blockIdx.x] = neg_acc;
            g_cnt_part[blockIdx.x] = cnt;
        }
    }
}

__global__ __launch_bounds__(1024)
void micro_loss_final_kernel(float* __restrict__ out, long long n_total) {
    float pos_acc = 0.0f, neg_acc = 0.0f;
    long long cnt = 0;
    // 1024 threads, each reads NBLOCKS/1024 = 2 partials
    for (int i = threadIdx.x; i < NBLOCKS; i += 1024) {
        pos_acc += g_pos_part[i];
        neg_acc += g_neg_part[i];
        cnt     += (long long)g_cnt_part[i];
    }
    // Warp reduce
    #pragma unroll
    for (int off = 16; off > 0; off >>= 1) {
        pos_acc += __shfl_down_sync(0xffffffffu, pos_acc, off);
        neg_acc += __shfl_down_sync(0xffffffffu, neg_acc, off);
        cnt     += __shfl_down_sync(0xffffffffu, cnt,     off);
    }
    __shared__ float s_pos[32];
    __shared__ float s_neg[32];
    __shared__ long long s_cnt[32];
    int lane = threadIdx.x & 31;
    int warp = threadIdx.x >> 5;
    if (lane == 0) { s_pos[warp] = pos_acc; s_neg[warp] = neg_acc; s_cnt[warp] = cnt; }
    __syncthreads();
    if (warp == 0) {
        pos_acc = (lane < 32) ? s_pos[lane] : 0.0f;
        neg_acc = (lane < 32) ? s_neg[lane] : 0.0f;
        cnt     = (lane < 32) ? s_cnt[lane] : 0;
        #pragma unroll
        for (int off = 16; off > 0; off >>= 1) {
            pos_acc += __shfl_down_sync(0xffffffffu, pos_acc, off);
            neg_acc += __shfl_down_sync(0xffffffffu, neg_acc, off);
            cnt     += __shfl_down_sync(0xffffffffu, cnt,     off);
        }
        if (lane == 0) {
            float n_pos = (float)cnt;
            float n_neg = (float)(n_total - cnt);
            out[0] = pos_acc / n_pos + neg_acc / n_neg;
        }
    }
}

extern "C" void kernel_launch(void* const* d_in, const int* in_sizes, int n_in,
                              void* d_out, int out_size) {
    const float* pred = (const float*)d_in[0];
    const int*   lbl  = (const int*)d_in[1];
    float* out = (float*)d_out;
    long long n = (long long)in_sizes[0];

    micro_loss_partial_kernel<<<NBLOCKS, NTHREADS>>>(pred, lbl, n);
    micro_loss_final_kernel<<<1, 1024>>>(out, n);
}

// round 4
// speedup vs baseline: 1.2945x; 1.2945x over previous
#include <cuda_runtime.h>
#include <cuda_bf16.h>
#include <math.h>

// ForMicroLoss: l = sum_{pos} softplus(-x)/n_pos + sum_{neg} softplus(x)/n_neg
// pred_y: fp32 [N*K], true_y: int32 [N*K] (labels in {0,1})
// Streaming reduction: 512 MB read, 4 B write. Single fused kernel.
//
// Per-element identity (t = log(1+exp(-|x|)), relu = max(x,0)):
//   pos contribution: softplus(-x) = t + relu - x
//   neg contribution: softplus( x) = t + relu
// So  c = t + relu - (lbl ? x : 0)  is correct either way; accumulate
// sum_all += c and sum_pos += (lbl ? c : 0); neg = all - pos.

#define NBLOCKS  2048
#define NTHREADS 256
#define TOTAL_T  (NBLOCKS * NTHREADS)

__device__ float g_all_part[NBLOCKS];
__device__ float g_pos_part[NBLOCKS];
__device__ int   g_cnt_part[NBLOCKS];
__device__ unsigned int g_ticket = 0;   // reset to 0 by the last block each call

__device__ __forceinline__ void accum_elem(float x, int lbl,
                                           float& all_acc, float& pos_acc) {
    float e    = __expf(-fabsf(x));          // FMUL + MUFU.EX2
    float t    = __logf(1.0f + e);           // FADD + MUFU.LG2 + FMUL
    float relu = fmaxf(x, 0.0f);
    float lx   = lbl ? x : 0.0f;
    float c    = t + relu - lx;
    all_acc += c;
    pos_acc += lbl ? c : 0.0f;
}

__global__ __launch_bounds__(NTHREADS)
void micro_loss_kernel(const float* __restrict__ pred,
                       const int*   __restrict__ lbl,
                       float* __restrict__ out,
                       long long n) {
    const long long tid    = (long long)blockIdx.x * NTHREADS + threadIdx.x;
    const long long stride = TOTAL_T;
    const long long n4     = n >> 2;

    const float4* __restrict__ pred4 = reinterpret_cast<const float4*>(pred);
    const int4*   __restrict__ lbl4  = reinterpret_cast<const int4*>(lbl);

    float all_acc = 0.0f, pos_acc = 0.0f;
    int cnt = 0;

    // Main loop, unrolled x4 with batched loads: 8 independent LDG.128s
    // in flight before any math (high MLP). At n = 8192*8192 this covers
    // everything exactly (32 vec4/thread -> 8 macro-iters, no tail).
    long long i = tid;
    for (; i + 3 * stride < n4; i += 4 * stride) {
        float4 p0 = pred4[i];
        float4 p1 = pred4[i +     stride];
        float4 p2 = pred4[i + 2 * stride];
        float4 p3 = pred4[i + 3 * stride];
        int4   l0 = lbl4 [i];
        int4   l1 = lbl4 [i +     stride];
        int4   l2 = lbl4 [i + 2 * stride];
        int4   l3 = lbl4 [i + 3 * stride];

        cnt += (l0.x + l0.y + l0.z + l0.w) + (l1.x + l1.y + l1.z + l1.w)
             + (l2.x + l2.y + l2.z + l2.w) + (l3.x + l3.y + l3.z + l3.w);

        accum_elem(p0.x, l0.x, all_acc, pos_acc);
        accum_elem(p0.y, l0.y, all_acc, pos_acc);
        accum_elem(p0.z, l0.z, all_acc, pos_acc);
        accum_elem(p0.w, l0.w, all_acc, pos_acc);
        accum_elem(p1.x, l1.x, all_acc, pos_acc);
        accum_elem(p1.y, l1.y, all_acc, pos_acc);
        accum_elem(p1.z, l1.z, all_acc, pos_acc);
        accum_elem(p1.w, l1.w, all_acc, pos_acc);
        accum_elem(p2.x, l2.x, all_acc, pos_acc);
        accum_elem(p2.y, l2.y, all_acc, pos_acc);
        accum_elem(p2.z, l2.z, all_acc, pos_acc);
        accum_elem(p2.w, l2.w, all_acc, pos_acc);
        accum_elem(p3.x, l3.x, all_acc, pos_acc);
        accum_elem(p3.y, l3.y, all_acc, pos_acc);
        accum_elem(p3.z, l3.z, all_acc, pos_acc);
        accum_elem(p3.w, l3.w, all_acc, pos_acc);
    }
    // Vec4 remainder
    for (; i < n4; i += stride) {
        float4 p = pred4[i];
        int4   l = lbl4[i];
        cnt += l.x + l.y + l.z + l.w;
        accum_elem(p.x, l.x, all_acc, pos_acc);
        accum_elem(p.y, l.y, all_acc, pos_acc);
        accum_elem(p.z, l.z, all_acc, pos_acc);
        accum_elem(p.w, l.w, all_acc, pos_acc);
    }
    // Scalar tail (n % 4 != 0) — not hit at this shape
    for (long long j = (n4 << 2) + tid; j < n; j += stride) {
        float x = pred[j];
        int   l = lbl[j];
        cnt += l;
        accum_elem(x, l, all_acc, pos_acc);
    }

    // Warp reduce
    #pragma unroll
    for (int off = 16; off > 0; off >>= 1) {
        all_acc += __shfl_down_sync(0xffffffffu, all_acc, off);
        pos_acc += __shfl_down_sync(0xffffffffu, pos_acc, off);
        cnt     += __shfl_down_sync(0xffffffffu, cnt,     off);
    }

    // Block reduce
    __shared__ float s_all[NTHREADS / 32];
    __shared__ float s_pos[NTHREADS / 32];
    __shared__ int   s_cnt[NTHREADS / 32];
    __shared__ bool  s_is_last;
    int lane = threadIdx.x & 31;
    int warp = threadIdx.x >> 5;
    if (lane == 0) { s_all[warp] = all_acc; s_pos[warp] = pos_acc; s_cnt[warp] = cnt; }
    __syncthreads();
    if (warp == 0) {
        all_acc = (lane < NTHREADS / 32) ? s_all[lane] : 0.0f;
        pos_acc = (lane < NTHREADS / 32) ? s_pos[lane] : 0.0f;
        cnt     = (lane < NTHREADS / 32) ? s_cnt[lane] : 0;
        #pragma unroll
        for (int off = 4; off > 0; off >>= 1) {
            all_acc += __shfl_down_sync(0xffffffffu, all_acc, off);
            pos_acc += __shfl_down_sync(0xffffffffu, pos_acc, off);
            cnt     += __shfl_down_sync(0xffffffffu, cnt,     off);
        }
        if (lane == 0) {
            g_all_part[blockIdx.x] = all_acc;
            g_pos_part[blockIdx.x] = pos_acc;
            g_cnt_part[blockIdx.x] = cnt;
            __threadfence();                       // publish partials
            unsigned int t = atomicAdd(&g_ticket, 1u);
            s_is_last = (t == NBLOCKS - 1);
        }
    }
    __syncthreads();

    // Last block to finish performs the final reduction (deterministic:
    // values and reduction order are identical regardless of which block
    // executes this). No block ever waits on another — no deadlock risk.
    if (s_is_last) {
        __threadfence();
        float fa = 0.0f, fp = 0.0f;
        int   fc = 0;
        #pragma unroll
        for (int k = 0; k < NBLOCKS / NTHREADS; k++) {
            int idx = threadIdx.x + k * NTHREADS;
            fa += g_all_part[idx];
            fp += g_pos_part[idx];
            fc += g_cnt_part[idx];
        }
        #pragma unroll
        for (int off = 16; off > 0; off >>= 1) {
            fa += __shfl_down_sync(0xffffffffu, fa, off);
            fp += __shfl_down_sync(0xffffffffu, fp, off);
            fc += __shfl_down_sync(0xffffffffu, fc, off);
        }
        __shared__ float f_all[NTHREADS / 32];
        __shared__ float f_pos[NTHREADS / 32];
        __shared__ int   f_cnt[NTHREADS / 32];
        if (lane == 0) { f_all[warp] = fa; f_pos[warp] = fp; f_cnt[warp] = fc; }
        __syncthreads();
        if (warp == 0) {
            fa = (lane < NTHREADS / 32) ? f_all[lane] : 0.0f;
            fp = (lane < NTHREADS / 32) ? f_pos[lane] : 0.0f;
            fc = (lane < NTHREADS / 32) ? f_cnt[lane] : 0;
            #pragma unroll
            for (int off = 4; off > 0; off >>= 1) {
                fa += __shfl_down_sync(0xffffffffu, fa, off);
                fp += __shfl_down_sync(0xffffffffu, fp, off);
                fc += __shfl_down_sync(0xffffffffu, fc, off);
            }
            if (lane == 0) {
                float neg_sum = fa - fp;
                float n_pos = (float)fc;
                float n_neg = (float)n - n_pos;
                out[0] = fp / n_pos + neg_sum / n_neg;
                g_ticket = 0;                      // re-arm for next replay
            }
        }
    }
}

extern "C" void kernel_launch(void* const* d_in, const int* in_sizes, int n_in,
                              void* d_out, int out_size) {
    const float* pred = (const float*)d_in[0];
    const int*   lbl  = (const int*)d_in[1];
    float* out = (float*)d_out;
    long long n = (long long)in_sizes[0];

    micro_loss_kernel<<<NBLOCKS, NTHREADS>>>(pred, lbl, out, n);
}